// round 15
// baseline (speedup 1.0000x reference)
#include <cuda_runtime.h>
#include <cstdint>
#include <math.h>

// Problem constants
#define Bb     16
#define Ss     384
#define Gg     384
#define NTOK   768
#define ECHAR  100
#define Dd     128
#define Tt     21
#define CSTART 19
#define CSTOP  20
#define BNROWS (Bb*NTOK)    // 12288
#define BSROWS (Bb*Ss)      // 6144

// scratch layout (floats)
#define OFF_XW     0u                       // [2][6144][256]      3,145,728
#define OFF_GATIN  3145728u                 // [12288][128]        1,572,864
#define OFF_HH     4718592u                 // [3][12288][256] interleaved 9,437,184
#define OFF_H2     14524416u                // [3][12288][21]        774,144
#define OFF_LPROJ  15298560u                // [6144][21]            129,024
#define OFF_GOUT   15427584u                // [3][6144][21]         387,072
#define OFF_FEATS  15814656u                // [6144][21]            129,024
#define OFF_HCAT   15943680u                // [3][12288][256]     9,437,184
#define OFF_ABM    25380864u                // [3][12288][24] words   884,736
#define SCRATCH_TOTAL 26265600u

__device__ float g_scratch[SCRATCH_TOTAL];

// dynamic smem sizes
#define SMEM_ATTN1 ((49152 + 768 + 768) * 4 + 8 * 256 * 8)  // 219,136 B
#define SMEM_ATTN2 (16128 * 4 + 768 * 4 + 8 * 256 * 8)      // 84,096 B

__device__ __forceinline__ float fsig(float x) {
    return 1.f / (1.f + __expf(-x));
}
__device__ __forceinline__ float ftanh(float x) {
    x = fminf(15.f, fmaxf(-15.f, x));
    float e = __expf(2.f * x);
    return (e - 1.f) / (e + 1.f);
}

// ---------------- adjacency -> bitmask (warp per row) ----------------
__global__ __launch_bounds__(256)
void adj_bitmask_kernel(const int* __restrict__ adj0, const int* __restrict__ adj1,
                        const int* __restrict__ adj2) {
    unsigned* abm = (unsigned*)(g_scratch + OFF_ABM);
    int gw = blockIdx.x * 8 + (threadIdx.x >> 5);
    int lane = threadIdx.x & 31;
    if (gw >= 3 * BNROWS) return;
    int z = gw / BNROWS;
    int row = gw - z * BNROWS;
    const int* adj = (z == 0) ? adj0 : (z == 1) ? adj1 : adj2;
    const int* arow = adj + (size_t)row * 768;
    unsigned myword = 0;
    #pragma unroll
    for (int q = 0; q < 24; q++) {
        unsigned bal = __ballot_sync(0xffffffffu, arow[q * 32 + lane] > 0);
        if (lane == q) myword = bal;
    }
    if (lane < 24) abm[(size_t)gw * 24 + lane] = myword;
}

// ---------------- gaz embedding gather ----------------
__global__ void embed_gaz_kernel(const int* __restrict__ gl,
                                 const float* __restrict__ tab) {
    int i = blockIdx.x * blockDim.x + threadIdx.x;
    if (i >= Bb * Gg * Dd) return;
    int r = i / Dd, f = i - r * Dd;
    int b = r / Gg, g = r - b * Gg;
    int idx = gl[r];
    if (idx < 0) idx = 0; if (idx >= 100000) idx = 99999;
    g_scratch[OFF_GATIN + ((size_t)b * NTOK + Ss + g) * Dd + f] =
        tab[(size_t)idx * Dd + f];
}

// ---------------- merged xw GEMM ----------------
__global__ __launch_bounds__(256)
void gemm_xw_kernel(const float* __restrict__ tab, const int* __restrict__ bc,
                    const float* __restrict__ wf, const float* __restrict__ bf,
                    const float* __restrict__ wb, const float* __restrict__ bb) {
    __shared__ __align__(16) float As[16][68];
    __shared__ __align__(16) float Bs[16][68];
    int tid = threadIdx.x;
    int tx = tid & 15, ty = tid >> 4;
    int rowBase = blockIdx.y * 64;
    int colBase = blockIdx.x * 64;
    int dirb = colBase >= 256;
    const float* Bm = dirb ? wb : wf;
    const float* bias = dirb ? bb : bf;
    int colLoc = colBase - (dirb ? 256 : 0);
    float* C = g_scratch + OFF_XW + (dirb ? (size_t)BSROWS * 256 : 0);
    float acc[4][4] = {};
    for (int k0 = 0; k0 < ECHAR; k0 += 16) {
        for (int l = tid; l < 1024; l += 256) {
            int r = l >> 4, kk = l & 15;
            int gk = k0 + kk;
            float v = 0.f;
            if (gk < ECHAR) {
                int ci = bc[rowBase + r];
                if (ci < 0) ci = 0; if (ci >= 8000) ci = 7999;
                v = tab[(size_t)ci * ECHAR + gk];
            }
            As[kk][r] = v;
        }
        for (int l = tid; l < 1024; l += 256) {
            int kk = l >> 6, c = l & 63;
            int gk = k0 + kk;
            Bs[kk][c] = (gk < ECHAR) ? Bm[(size_t)(colLoc + c) * ECHAR + gk] : 0.f;
        }
        __syncthreads();
        #pragma unroll
        for (int kk = 0; kk < 16; kk++) {
            float4 av = *(const float4*)&As[kk][ty * 4];
            float4 bv = *(const float4*)&Bs[kk][tx * 4];
            float a[4] = {av.x, av.y, av.z, av.w};
            float b[4] = {bv.x, bv.y, bv.z, bv.w};
            #pragma unroll
            for (int i = 0; i < 4; i++)
                #pragma unroll
                for (int j = 0; j < 4; j++)
                    acc[i][j] += a[i] * b[j];
        }
        __syncthreads();
    }
    #pragma unroll
    for (int i = 0; i < 4; i++) {
        int row = rowBase + ty * 4 + i;
        #pragma unroll
        for (int j = 0; j < 4; j++) {
            int col = colLoc + tx * 4 + j;
            C[(size_t)row * 256 + col] = acc[i][j] + bias[col];
        }
    }
}

// ---------------- generic tiled fp32 GEMM (used for lproj) ----------------
__global__ __launch_bounds__(256)
void gemm_kernel(unsigned aoff, const float* __restrict__ Bm,
                 const float* __restrict__ bias,
                 unsigned coff, int M, int N, int K, int transB,
                 int arpb, int astr) {
    float* C = g_scratch + coff;
    __shared__ __align__(16) float As[16][68];
    __shared__ __align__(16) float Bs[16][68];
    int tid = threadIdx.x;
    int tx = tid & 15, ty = tid >> 4;
    int rowBase = blockIdx.y * 64;
    int colBase = blockIdx.x * 64;
    float acc[4][4] = {};
    for (int k0 = 0; k0 < K; k0 += 16) {
        for (int l = tid; l < 1024; l += 256) {
            int r = l >> 4, kk = l & 15;
            int gr = rowBase + r, gk = k0 + kk;
            float v = 0.f;
            if (gr < M && gk < K) {
                int sr = (gr / arpb) * astr + (gr % arpb);
                v = g_scratch[aoff + (size_t)sr * K + gk];
            }
            As[kk][r] = v;
        }
        for (int l = tid; l < 1024; l += 256) {
            int kk = l >> 6, c = l & 63;
            int gk = k0 + kk, gc = colBase + c;
            float v = 0.f;
            if (gk < K && gc < N)
                v = transB ? Bm[(size_t)gc * K + gk] : Bm[(size_t)gk * N + gc];
            Bs[kk][c] = v;
        }
        __syncthreads();
        #pragma unroll
        for (int kk = 0; kk < 16; kk++) {
            float4 av = *(const float4*)&As[kk][ty * 4];
            float4 bv = *(const float4*)&Bs[kk][tx * 4];
            float a[4] = {av.x, av.y, av.z, av.w};
            float b[4] = {bv.x, bv.y, bv.z, bv.w};
            #pragma unroll
            for (int i = 0; i < 4; i++)
                #pragma unroll
                for (int j = 0; j < 4; j++)
                    acc[i][j] += a[i] * b[j];
        }
        __syncthreads();
    }
    #pragma unroll
    for (int i = 0; i < 4; i++) {
        int row = rowBase + ty * 4 + i;
        if (row >= M) continue;
        #pragma unroll
        for (int j = 0; j < 4; j++) {
            int col = colBase + tx * 4 + j;
            if (col >= N) continue;
            float v = acc[i][j];
            if (bias) v += bias[col];
            C[(size_t)row * N + col] = v;
        }
    }
}

// ---------------- HH GEMM: gatin @ WhCat -> HH interleaved [row][m*64+f] ----------------
// 128x128 tile, 8x8 per thread. grid (2 col-tiles, 48 = b*3+tl, 3 z); half selects rows.
__global__ __launch_bounds__(256)
void gemm_hh_kernel(const float* __restrict__ WhAll, int half) {
    int z = blockIdx.z;
    int colBase = blockIdx.x * 128;
    int y = blockIdx.y;
    int b = y / 3, tl = y % 3;
    int rowBase = b * 768 + half * 384 + tl * 128;
    const float* A = g_scratch + OFF_GATIN;
    float* C = g_scratch + OFF_HH + (size_t)z * BNROWS * 256;
    __shared__ __align__(16) float As[16][132];
    __shared__ __align__(16) float Bs[16][132];
    int tid = threadIdx.x;
    int tx = tid & 15, ty = tid >> 4;
    float acc[8][8] = {};
    for (int k0 = 0; k0 < 128; k0 += 16) {
        for (int l = tid; l < 2048; l += 256) {
            int r = l >> 4, kk = l & 15;
            As[kk][r] = A[(size_t)(rowBase + r) * 128 + k0 + kk];
        }
        for (int l = tid; l < 2048; l += 256) {
            int kk = l >> 7, c = l & 127;
            int gc = colBase + c;
            int m = gc >> 6, f = gc & 63;
            Bs[kk][c] = WhAll[(((size_t)(z * 4 + m)) * 128 + k0 + kk) * 64 + f];
        }
        __syncthreads();
        #pragma unroll
        for (int kk = 0; kk < 16; kk++) {
            float a[8], bv[8];
            *(float4*)&a[0]  = *(const float4*)&As[kk][ty * 8];
            *(float4*)&a[4]  = *(const float4*)&As[kk][ty * 8 + 4];
            *(float4*)&bv[0] = *(const float4*)&Bs[kk][tx * 8];
            *(float4*)&bv[4] = *(const float4*)&Bs[kk][tx * 8 + 4];
            #pragma unroll
            for (int i = 0; i < 8; i++)
                #pragma unroll
                for (int j = 0; j < 8; j++)
                    acc[i][j] += a[i] * bv[j];
        }
        __syncthreads();
    }
    #pragma unroll
    for (int i = 0; i < 8; i++) {
        int row = rowBase + ty * 8 + i;
        float4 v0, v1;
        v0.x = acc[i][0]; v0.y = acc[i][1]; v0.z = acc[i][2]; v0.w = acc[i][3];
        v1.x = acc[i][4]; v1.y = acc[i][5]; v1.z = acc[i][6]; v1.w = acc[i][7];
        *(float4*)&C[(size_t)row * 256 + colBase + tx * 8] = v0;
        *(float4*)&C[(size_t)row * 256 + colBase + tx * 8 + 4] = v1;
    }
}

// ---------------- h2 projection GEMM ----------------
__global__ __launch_bounds__(256)
void gemm_h2_kernel(const float* __restrict__ WoAll) {
    int z = blockIdx.z;
    const float* A = g_scratch + OFF_HCAT + (size_t)z * BNROWS * 256;
    const float* B = WoAll + (size_t)z * 256 * Tt;
    float* C = g_scratch + OFF_H2 + (size_t)z * BNROWS * Tt;
    __shared__ __align__(16) float As[16][68];
    __shared__ __align__(16) float Bs[16][68];
    int tid = threadIdx.x;
    int tx = tid & 15, ty = tid >> 4;
    int rowBase = blockIdx.y * 64;
    float acc[4][4] = {};
    for (int k0 = 0; k0 < 256; k0 += 16) {
        for (int l = tid; l < 1024; l += 256) {
            int r = l >> 4, kk = l & 15;
            As[kk][r] = A[(size_t)(rowBase + r) * 256 + k0 + kk];
        }
        for (int l = tid; l < 1024; l += 256) {
            int kk = l >> 6, c = l & 63;
            Bs[kk][c] = (c < Tt) ? B[(size_t)(k0 + kk) * Tt + c] : 0.f;
        }
        __syncthreads();
        #pragma unroll
        for (int kk = 0; kk < 16; kk++) {
            float4 av = *(const float4*)&As[kk][ty * 4];
            float4 bv = *(const float4*)&Bs[kk][tx * 4];
            float a[4] = {av.x, av.y, av.z, av.w};
            float b[4] = {bv.x, bv.y, bv.z, bv.w};
            #pragma unroll
            for (int i = 0; i < 4; i++)
                #pragma unroll
                for (int j = 0; j < 4; j++)
                    acc[i][j] += a[i] * b[j];
        }
        __syncthreads();
    }
    #pragma unroll
    for (int i = 0; i < 4; i++) {
        int row = rowBase + ty * 4 + i;
        #pragma unroll
        for (int j = 0; j < 4; j++) {
            int col = tx * 4 + j;
            if (col < Tt)
                C[(size_t)row * Tt + col] = acc[i][j];
        }
    }
}

// ---------------- BiLSTM (round-11 form) ----------------
__global__ __launch_bounds__(256)
void lstm_kernel(const float* __restrict__ whh_f, const float* __restrict__ whh_b) {
    int dir = blockIdx.x & 1, b = blockIdx.x >> 1;
    const float* whh = dir ? whh_b : whh_f;
    int g = threadIdx.x;
    float w[64];
    #pragma unroll
    for (int j = 0; j < 64; j++) w[j] = whh[g * 64 + j];
    __shared__ __align__(16) float hsh[64];
    __shared__ float gates[256];
    float creg = 0.f;
    if (g < 64) hsh[g] = 0.f;
    __syncthreads();
    const float* xwd = g_scratch + OFF_XW + (size_t)dir * BSROWS * 256
                       + (size_t)b * Ss * 256;
    float* gat_in = g_scratch + OFF_GATIN;
    int t = dir ? (Ss - 1) : 0;
    int dt = dir ? -1 : 1;
    bool iscell = (g >= 128 && g < 192);
    float xnext = xwd[(size_t)t * 256 + g];
    for (int step = 0; step < Ss; step++, t += dt) {
        float acc = xnext;
        if (step + 1 < Ss) xnext = xwd[(size_t)(t + dt) * 256 + g];
        const float4* h4 = (const float4*)hsh;
        float a0 = 0.f, a1 = 0.f, a2 = 0.f, a3 = 0.f;
        #pragma unroll
        for (int j4 = 0; j4 < 16; j4++) {
            float4 hv = h4[j4];
            a0 += hv.x * w[4 * j4];
            a1 += hv.y * w[4 * j4 + 1];
            a2 += hv.z * w[4 * j4 + 2];
            a3 += hv.w * w[4 * j4 + 3];
        }
        acc += (a0 + a1) + (a2 + a3);
        gates[g] = iscell ? ftanh(acc) : fsig(acc);
        __syncthreads();
        if (g < 64) {
            creg = gates[64 + g] * creg + gates[g] * gates[128 + g];
            float h = gates[192 + g] * ftanh(creg);
            hsh[g] = h;
            gat_in[((size_t)b * NTOK + t) * Dd + dir * 64 + g] = h;
        }
        __syncthreads();
    }
}

// ---------------- GAT layer-1 aggregation (bitmask adjacency, f1/f2 in-kernel) ----------------
__global__ __launch_bounds__(256)
void attn1_agg_kernel(const float* __restrict__ ahAll) {
    extern __shared__ __align__(16) float smem[];
    float* hsm = smem;                               // 49152
    float* f1s = smem + 49152;                       // 768
    float* f2s = smem + 49152 + 768;                 // 768
    float2* psj = (float2*)(smem + 49152 + 1536);    // 8 x 256
    int z = blockIdx.z;
    int m = blockIdx.y >> 4, b = blockIdx.y & 15;
    int chunk = blockIdx.x;
    int hm = z * 4 + m;
    int tid = threadIdx.x, lane = tid & 31, w = tid >> 5;
    const unsigned* abm = (const unsigned*)(g_scratch + OFF_ABM)
                          + ((size_t)z * BNROWS + (size_t)b * 768) * 24;

    // load panel: HH interleaved rows b*768.., cols m*64..m*64+63
    const float4* hbase = (const float4*)(g_scratch + OFF_HH
                          + ((size_t)z * BNROWS + (size_t)b * 768) * 256 + m * 64);
    float4* hdst = (float4*)hsm;
    for (int l = tid; l < 12288; l += 256) {
        int r = l >> 4, q = l & 15;
        hdst[l] = hbase[(size_t)r * 64 + q];
    }
    __syncthreads();

    // f1/f2 for all 768 panel rows (warp-cooperative dots)
    {
        const float* ah = ahAll + (size_t)hm * 128;
        float a1a = ah[lane * 2], a1b = ah[lane * 2 + 1];
        float a2a = ah[64 + lane * 2], a2b = ah[64 + lane * 2 + 1];
        for (int r = w; r < 768; r += 8) {
            float2 hv = ((const float2*)(hsm + r * 64))[lane];
            float s1 = hv.x * a1a + hv.y * a1b;
            float s2 = hv.x * a2a + hv.y * a2b;
            #pragma unroll
            for (int off = 16; off > 0; off >>= 1) {
                s1 += __shfl_xor_sync(0xffffffffu, s1, off);
                s2 += __shfl_xor_sync(0xffffffffu, s2, off);
            }
            if (lane == 0) { f1s[r] = s1; f2s[r] = s2; }
        }
    }
    __syncthreads();

    float2* mypsj = psj + w * 256;
    float* hcat = g_scratch + OFF_HCAT + (size_t)z * BNROWS * 256;
    const float2* h2p = (const float2*)hsm;

    for (int i = chunk * 384 + w; i < chunk * 384 + 384; i += 8) {
        unsigned word = (lane < 24) ? abm[(size_t)i * 24 + lane] : 0u;
        int c = __popc(word);
        int pos = c;
        #pragma unroll
        for (int off = 1; off < 32; off <<= 1) {
            int n = __shfl_up_sync(0xffffffffu, pos, off);
            if (lane >= off) pos += n;
        }
        int nnz = __shfl_sync(0xffffffffu, pos, 31);
        pos -= c;
        float f1i = f1s[i];
        unsigned wtmp = word;
        while (wtmp) {
            int r = __ffs(wtmp) - 1;
            wtmp &= wtmp - 1;
            int j = lane * 32 + r;
            float e = f1i + f2s[j];
            e = e > 0.f ? e : 0.2f * e;
            mypsj[pos] = make_float2(e, __int_as_float(j));
            pos++;
        }
        __syncwarp();
        float mx = -3e38f;
        for (int idx = lane; idx < nnz; idx += 32) mx = fmaxf(mx, mypsj[idx].x);
        #pragma unroll
        for (int off = 16; off > 0; off >>= 1)
            mx = fmaxf(mx, __shfl_xor_sync(0xffffffffu, mx, off));
        float sm = 0.f;
        for (int idx = lane; idx < nnz; idx += 32) {
            float p = expf(mypsj[idx].x - mx);
            mypsj[idx].x = p;
            sm += p;
        }
        #pragma unroll
        for (int off = 16; off > 0; off >>= 1)
            sm += __shfl_xor_sync(0xffffffffu, sm, off);
        __syncwarp();
        float2 acc = make_float2(0.f, 0.f);
        #pragma unroll 2
        for (int idx = 0; idx < nnz; idx++) {
            float2 pj = mypsj[idx];
            int j = __float_as_int(pj.y);
            float2 hv = h2p[j * 32 + lane];
            acc.x += pj.x * hv.x;
            acc.y += pj.x * hv.y;
        }
        acc.x /= sm;
        acc.y /= sm;
        acc.x = acc.x > 0.f ? acc.x : expm1f(acc.x);
        acc.y = acc.y > 0.f ? acc.y : expm1f(acc.y);
        ((float2*)(hcat + ((size_t)b * 768 + i) * 256 + m * 64))[lane] = acc;
        __syncwarp();
    }
}

// ---------------- GAT layer-2 (bitmask adjacency, fused f1b/f2b) ----------------
__global__ __launch_bounds__(256)
void attn2_panel_kernel(const float* __restrict__ aoAll) {
    extern __shared__ __align__(16) float smem[];
    float* h2sm = smem;
    float* f2s = smem + 16128;
    float2* psj = (float2*)(smem + 16128 + 768);
    int b = blockIdx.x, z = blockIdx.y;
    const float* ao = aoAll + (size_t)z * 42;
    const float* h2g = g_scratch + OFF_H2 + ((size_t)z * BNROWS + (size_t)b * 768) * 21;
    int tid = threadIdx.x, lane = tid & 31, w = tid >> 5;
    const unsigned* abm = (const unsigned*)(g_scratch + OFF_ABM)
                          + ((size_t)z * BNROWS + (size_t)b * 768) * 24;

    for (int l = tid; l < 16128; l += 256) h2sm[l] = h2g[l];
    __syncthreads();
    for (int j = tid; j < 768; j += 256) {
        float s = 0.f;
        #pragma unroll
        for (int t = 0; t < 21; t++) s += h2sm[j * 21 + t] * ao[21 + t];
        f2s[j] = s;
    }
    __syncthreads();

    float2* mypsj = psj + w * 256;
    float* gout = g_scratch + OFF_GOUT + (size_t)z * BSROWS * Tt;
    float ao1 = (lane < 21) ? ao[lane] : 0.f;

    for (int i = w; i < Ss; i += 8) {
        float f1i = (lane < 21) ? h2sm[i * 21 + lane] * ao1 : 0.f;
        #pragma unroll
        for (int off = 16; off > 0; off >>= 1)
            f1i += __shfl_xor_sync(0xffffffffu, f1i, off);
        unsigned word = (lane < 24) ? abm[(size_t)i * 24 + lane] : 0u;
        int c = __popc(word);
        int pos = c;
        #pragma unroll
        for (int off = 1; off < 32; off <<= 1) {
            int n = __shfl_up_sync(0xffffffffu, pos, off);
            if (lane >= off) pos += n;
        }
        int nnz = __shfl_sync(0xffffffffu, pos, 31);
        pos -= c;
        unsigned wtmp = word;
        while (wtmp) {
            int r = __ffs(wtmp) - 1;
            wtmp &= wtmp - 1;
            int j = lane * 32 + r;
            float e = f1i + f2s[j];
            e = e > 0.f ? e : 0.2f * e;
            mypsj[pos] = make_float2(e, __int_as_float(j));
            pos++;
        }
        __syncwarp();
        float mx = -3e38f;
        for (int idx = lane; idx < nnz; idx += 32) mx = fmaxf(mx, mypsj[idx].x);
        #pragma unroll
        for (int off = 16; off > 0; off >>= 1)
            mx = fmaxf(mx, __shfl_xor_sync(0xffffffffu, mx, off));
        float sm = 0.f;
        for (int idx = lane; idx < nnz; idx += 32) {
            float p = expf(mypsj[idx].x - mx);
            mypsj[idx].x = p;
            sm += p;
        }
        #pragma unroll
        for (int off = 16; off > 0; off >>= 1)
            sm += __shfl_xor_sync(0xffffffffu, sm, off);
        __syncwarp();
        if (lane < 21) {
            float acc = 0.f;
            #pragma unroll 2
            for (int idx = 0; idx < nnz; idx++) {
                float2 pj = mypsj[idx];
                int j = __float_as_int(pj.y);
                acc += pj.x * h2sm[j * 21 + lane];
            }
            acc /= sm;
            acc = acc > 0.f ? acc : expm1f(acc);
            gout[((size_t)b * Ss + i) * 21 + lane] = acc;
        }
        __syncwarp();
    }
}

// ---------------- fuse ----------------
__global__ void fuse_kernel(const float* __restrict__ fw) {
    int i = blockIdx.x * blockDim.x + threadIdx.x;
    if (i >= Bb * Ss * Tt) return;
    const float* lproj = g_scratch + OFF_LPROJ;
    const float* g0 = g_scratch + OFF_GOUT;
    const float* g1 = g0 + BSROWS * Tt;
    const float* g2 = g1 + BSROWS * Tt;
    g_scratch[OFF_FEATS + i] =
        fw[0] * lproj[i] + fw[1] * g0[i] + fw[2] * g1[i] + fw[3] * g2[i];
}

// ---------------- Viterbi (float32 output) ----------------
__global__ __launch_bounds__(32)
void viterbi_kernel(const float* __restrict__ trans,
                    const int* __restrict__ mask, float* __restrict__ outv) {
    const float* feats = g_scratch + OFF_FEATS;
    int b = blockIdx.x;
    int tid = threadIdx.x;
    __shared__ float part[21], np[21];
    __shared__ float trsh[441];
    __shared__ short bps[Ss * Tt];
    __shared__ int tags[Ss];
    for (int l = tid; l < 441; l += 32) trsh[l] = trans[l];
    __syncthreads();
    if (tid < 21)
        part[tid] = feats[((size_t)b * Ss) * Tt + tid] + trsh[CSTART * 21 + tid];
    __syncthreads();
    for (int t = 1; t < Ss; t++) {
        if (tid < 21) {
            float ft = feats[((size_t)b * Ss + t) * Tt + tid];
            float best = -3e38f; int bi = 0;
            #pragma unroll
            for (int p = 0; p < 21; p++) {
                float v = part[p] + trsh[p * 21 + tid] + ft;
                if (v > best) { best = v; bi = p; }
            }
            int m = mask[b * Ss + t];
            np[tid] = (m > 0) ? best : part[tid];
            bps[t * Tt + tid] = (short)((m > 0) ? bi : tid);
        }
        __syncthreads();
        if (tid < 21) part[tid] = np[tid];
        __syncthreads();
    }
    if (tid == 0) {
        float best = -3e38f; int bt = 0;
        for (int p = 0; p < 21; p++) {
            float v = part[p] + trsh[p * 21 + CSTOP];
            if (v > best) { best = v; bt = p; }
        }
        tags[Ss - 1] = bt;
        int tag = bt;
        for (int t = Ss - 1; t >= 1; t--) {
            tag = (int)bps[t * Tt + tag];
            tags[t - 1] = tag;
        }
    }
    __syncthreads();
    for (int t = tid; t < Ss; t += 32)
        outv[(size_t)b * Ss + t] = (float)tags[t];
}

// ---------------- launch ----------------
extern "C" void kernel_launch(void* const* d_in, const int* in_sizes, int n_in,
                              void* d_out, int out_size) {
    const int*   batch_char = (const int*)d_in[0];
    const int*   gaz_list   = (const int*)d_in[2];
    const int*   adj0       = (const int*)d_in[3];
    const int*   adj1       = (const int*)d_in[4];
    const int*   adj2       = (const int*)d_in[5];
    const int*   mask       = (const int*)d_in[6];
    const float* char_table = (const float*)d_in[7];
    const float* gaz_table  = (const float*)d_in[8];
    const float* w_ih_f     = (const float*)d_in[9];
    const float* w_hh_f     = (const float*)d_in[10];
    const float* b_f        = (const float*)d_in[11];
    const float* w_ih_b     = (const float*)d_in[12];
    const float* w_hh_b     = (const float*)d_in[13];
    const float* b_b        = (const float*)d_in[14];
    const float* h2h_W      = (const float*)d_in[15];
    const float* h2h_b      = (const float*)d_in[16];
    const float* gat_Wh     = (const float*)d_in[17];
    const float* gat_ah     = (const float*)d_in[18];
    const float* gat_Wo     = (const float*)d_in[19];
    const float* gat_ao     = (const float*)d_in[20];
    const float* fuse_w     = (const float*)d_in[21];
    const float* trans      = (const float*)d_in[22];

    static cudaStream_t s1 = nullptr;
    static cudaEvent_t evA = nullptr, evB = nullptr;
    if (!s1) {
        cudaStreamCreate(&s1);
        cudaEventCreateWithFlags(&evA, cudaEventDisableTiming);
        cudaEventCreateWithFlags(&evB, cudaEventDisableTiming);
    }
    cudaFuncSetAttribute(attn1_agg_kernel,
                         cudaFuncAttributeMaxDynamicSharedMemorySize, SMEM_ATTN1);
    cudaFuncSetAttribute(attn2_panel_kernel,
                         cudaFuncAttributeMaxDynamicSharedMemorySize, SMEM_ATTN2);

    // fork: side stream does adjacency bitmasks + gaz embedding + gaz-half HH GEMM
    cudaEventRecord(evA, 0);
    cudaStreamWaitEvent(s1, evA, 0);
    adj_bitmask_kernel<<<(3 * BNROWS + 7) / 8, 256, 0, s1>>>(adj0, adj1, adj2);
    embed_gaz_kernel<<<(Bb * Gg * Dd + 255) / 256, 256, 0, s1>>>(gaz_list, gaz_table);
    gemm_hh_kernel<<<dim3(2, 48, 3), 256, 0, s1>>>(gat_Wh, 1);
    cudaEventRecord(evB, s1);

    // main stream: xw GEMM -> lstm -> lproj -> lstm-half HH GEMM
    gemm_xw_kernel<<<dim3(8, 96), 256>>>(char_table, batch_char,
                                         w_ih_f, b_f, w_ih_b, b_b);
    lstm_kernel<<<32, 256>>>(w_hh_f, w_hh_b);
    gemm_kernel<<<dim3(1, 96), 256>>>(OFF_GATIN, h2h_W, h2h_b,
                                      OFF_LPROJ, BSROWS, Tt, Dd, 1, Ss, NTOK);
    gemm_hh_kernel<<<dim3(2, 48, 3), 256>>>(gat_Wh, 0);

    // join, then the rest of the GAT pipeline
    cudaStreamWaitEvent(0, evB, 0);
    attn1_agg_kernel<<<dim3(2, 64, 3), 256, SMEM_ATTN1>>>(gat_ah);
    gemm_h2_kernel<<<dim3(1, 192, 3), 256>>>(gat_Wo);
    attn2_panel_kernel<<<dim3(Bb, 3), 256, SMEM_ATTN2>>>(gat_ao);

    fuse_kernel<<<(Bb * Ss * Tt + 255) / 256, 256>>>(fuse_w);
    viterbi_kernel<<<Bb, 32>>>(trans, mask, (float*)d_out);
}

// round 16
// speedup vs baseline: 1.8452x; 1.8452x over previous
#include <cuda_runtime.h>
#include <cstdint>
#include <math.h>

// Problem constants
#define Bb     16
#define Ss     384
#define Gg     384
#define NTOK   768
#define ECHAR  100
#define Dd     128
#define Tt     21
#define CSTART 19
#define CSTOP  20
#define BNROWS (Bb*NTOK)    // 12288
#define BSROWS (Bb*Ss)      // 6144

// scratch layout (floats)
#define OFF_XW     0u                       // [2][6144][256]      3,145,728
#define OFF_GATIN  3145728u                 // [12288][128]        1,572,864
#define OFF_HH     4718592u                 // [3][4][12288][64]   9,437,184
#define OFF_F1     14155776u                // [3][4][12288]         147,456
#define OFF_F2     14303232u                //                       147,456
#define OFF_H2     14524416u                // [3][12288][21]        774,144
#define OFF_LPROJ  15298560u                // [6144][21]            129,024
#define OFF_GOUT   15427584u                // [3][6144][21]         387,072
#define OFF_FEATS  15814656u                // [6144][21]            129,024
#define OFF_HCAT   15943680u                // [3][12288][256]     9,437,184
#define OFF_ABM    25380864u                // [3][12288][24] words   884,736
#define SCRATCH_TOTAL 26265600u

__device__ float g_scratch[SCRATCH_TOTAL];

// dynamic smem sizes
#define SMEM_ATTN1 ((49152 + 768) * 4 + 8 * 256 * 8)   // 216,064 B
#define SMEM_ATTN2 (16128 * 4 + 768 * 4 + 8 * 256 * 8) // 84,096 B

__device__ __forceinline__ float fsig(float x) {
    return 1.f / (1.f + __expf(-x));
}
__device__ __forceinline__ float ftanh(float x) {
    x = fminf(15.f, fmaxf(-15.f, x));
    float e = __expf(2.f * x);
    return (e - 1.f) / (e + 1.f);
}

// ---------------- adjacency -> bitmask (warp per row) ----------------
__global__ __launch_bounds__(256)
void adj_bitmask_kernel(const int* __restrict__ adj0, const int* __restrict__ adj1,
                        const int* __restrict__ adj2) {
    unsigned* abm = (unsigned*)(g_scratch + OFF_ABM);
    int gw = blockIdx.x * 8 + (threadIdx.x >> 5);
    int lane = threadIdx.x & 31;
    if (gw >= 3 * BNROWS) return;
    int z = gw / BNROWS;
    int row = gw - z * BNROWS;
    const int* adj = (z == 0) ? adj0 : (z == 1) ? adj1 : adj2;
    const int* arow = adj + (size_t)row * 768;
    unsigned myword = 0;
    #pragma unroll
    for (int q = 0; q < 24; q++) {
        unsigned bal = __ballot_sync(0xffffffffu, arow[q * 32 + lane] > 0);
        if (lane == q) myword = bal;
    }
    if (lane < 24) abm[(size_t)gw * 24 + lane] = myword;
}

// ---------------- gaz embedding gather ----------------
__global__ void embed_gaz_kernel(const int* __restrict__ gl,
                                 const float* __restrict__ tab) {
    int i = blockIdx.x * blockDim.x + threadIdx.x;
    if (i >= Bb * Gg * Dd) return;
    int r = i / Dd, f = i - r * Dd;
    int b = r / Gg, g = r - b * Gg;
    int idx = gl[r];
    if (idx < 0) idx = 0; if (idx >= 100000) idx = 99999;
    g_scratch[OFF_GATIN + ((size_t)b * NTOK + Ss + g) * Dd + f] =
        tab[(size_t)idx * Dd + f];
}

// ---------------- merged xw GEMM ----------------
__global__ __launch_bounds__(256)
void gemm_xw_kernel(const float* __restrict__ tab, const int* __restrict__ bc,
                    const float* __restrict__ wf, const float* __restrict__ bf,
                    const float* __restrict__ wb, const float* __restrict__ bb) {
    __shared__ __align__(16) float As[16][68];
    __shared__ __align__(16) float Bs[16][68];
    int tid = threadIdx.x;
    int tx = tid & 15, ty = tid >> 4;
    int rowBase = blockIdx.y * 64;
    int colBase = blockIdx.x * 64;
    int dirb = colBase >= 256;
    const float* Bm = dirb ? wb : wf;
    const float* bias = dirb ? bb : bf;
    int colLoc = colBase - (dirb ? 256 : 0);
    float* C = g_scratch + OFF_XW + (dirb ? (size_t)BSROWS * 256 : 0);
    float acc[4][4] = {};
    for (int k0 = 0; k0 < ECHAR; k0 += 16) {
        for (int l = tid; l < 1024; l += 256) {
            int r = l >> 4, kk = l & 15;
            int gk = k0 + kk;
            float v = 0.f;
            if (gk < ECHAR) {
                int ci = bc[rowBase + r];
                if (ci < 0) ci = 0; if (ci >= 8000) ci = 7999;
                v = tab[(size_t)ci * ECHAR + gk];
            }
            As[kk][r] = v;
        }
        for (int l = tid; l < 1024; l += 256) {
            int kk = l >> 6, c = l & 63;
            int gk = k0 + kk;
            Bs[kk][c] = (gk < ECHAR) ? Bm[(size_t)(colLoc + c) * ECHAR + gk] : 0.f;
        }
        __syncthreads();
        #pragma unroll
        for (int kk = 0; kk < 16; kk++) {
            float4 av = *(const float4*)&As[kk][ty * 4];
            float4 bv = *(const float4*)&Bs[kk][tx * 4];
            float a[4] = {av.x, av.y, av.z, av.w};
            float b[4] = {bv.x, bv.y, bv.z, bv.w};
            #pragma unroll
            for (int i = 0; i < 4; i++)
                #pragma unroll
                for (int j = 0; j < 4; j++)
                    acc[i][j] += a[i] * b[j];
        }
        __syncthreads();
    }
    #pragma unroll
    for (int i = 0; i < 4; i++) {
        int row = rowBase + ty * 4 + i;
        #pragma unroll
        for (int j = 0; j < 4; j++) {
            int col = colLoc + tx * 4 + j;
            C[(size_t)row * 256 + col] = acc[i][j] + bias[col];
        }
    }
}

// ---------------- generic tiled fp32 GEMM ----------------
__global__ __launch_bounds__(256)
void gemm_kernel(unsigned aoff, const float* __restrict__ Bm,
                 const float* __restrict__ bias,
                 unsigned coff, int M, int N, int K, int transB,
                 int arpb, int astr) {
    float* C = g_scratch + coff;
    __shared__ __align__(16) float As[16][68];
    __shared__ __align__(16) float Bs[16][68];
    int tid = threadIdx.x;
    int tx = tid & 15, ty = tid >> 4;
    int rowBase = blockIdx.y * 64;
    int colBase = blockIdx.x * 64;
    float acc[4][4] = {};
    for (int k0 = 0; k0 < K; k0 += 16) {
        for (int l = tid; l < 1024; l += 256) {
            int r = l >> 4, kk = l & 15;
            int gr = rowBase + r, gk = k0 + kk;
            float v = 0.f;
            if (gr < M && gk < K) {
                int sr = (gr / arpb) * astr + (gr % arpb);
                v = g_scratch[aoff + (size_t)sr * K + gk];
            }
            As[kk][r] = v;
        }
        for (int l = tid; l < 1024; l += 256) {
            int kk = l >> 6, c = l & 63;
            int gk = k0 + kk, gc = colBase + c;
            float v = 0.f;
            if (gk < K && gc < N)
                v = transB ? Bm[(size_t)gc * K + gk] : Bm[(size_t)gk * N + gc];
            Bs[kk][c] = v;
        }
        __syncthreads();
        #pragma unroll
        for (int kk = 0; kk < 16; kk++) {
            float4 av = *(const float4*)&As[kk][ty * 4];
            float4 bv = *(const float4*)&Bs[kk][tx * 4];
            float a[4] = {av.x, av.y, av.z, av.w};
            float b[4] = {bv.x, bv.y, bv.z, bv.w};
            #pragma unroll
            for (int i = 0; i < 4; i++)
                #pragma unroll
                for (int j = 0; j < 4; j++)
                    acc[i][j] += a[i] * b[j];
        }
        __syncthreads();
    }
    #pragma unroll
    for (int i = 0; i < 4; i++) {
        int row = rowBase + ty * 4 + i;
        if (row >= M) continue;
        #pragma unroll
        for (int j = 0; j < 4; j++) {
            int col = colBase + tx * 4 + j;
            if (col >= N) continue;
            float v = acc[i][j];
            if (bias) v += bias[col];
            C[(size_t)row * N + col] = v;
        }
    }
}

// ---------------- h2 projection GEMM ----------------
__global__ __launch_bounds__(256)
void gemm_h2_kernel(const float* __restrict__ WoAll) {
    int z = blockIdx.z;
    const float* A = g_scratch + OFF_HCAT + (size_t)z * BNROWS * 256;
    const float* B = WoAll + (size_t)z * 256 * Tt;
    float* C = g_scratch + OFF_H2 + (size_t)z * BNROWS * Tt;
    __shared__ __align__(16) float As[16][68];
    __shared__ __align__(16) float Bs[16][68];
    int tid = threadIdx.x;
    int tx = tid & 15, ty = tid >> 4;
    int rowBase = blockIdx.y * 64;
    float acc[4][4] = {};
    for (int k0 = 0; k0 < 256; k0 += 16) {
        for (int l = tid; l < 1024; l += 256) {
            int r = l >> 4, kk = l & 15;
            As[kk][r] = A[(size_t)(rowBase + r) * 256 + k0 + kk];
        }
        for (int l = tid; l < 1024; l += 256) {
            int kk = l >> 6, c = l & 63;
            Bs[kk][c] = (c < Tt) ? B[(size_t)(k0 + kk) * Tt + c] : 0.f;
        }
        __syncthreads();
        #pragma unroll
        for (int kk = 0; kk < 16; kk++) {
            float4 av = *(const float4*)&As[kk][ty * 4];
            float4 bv = *(const float4*)&Bs[kk][tx * 4];
            float a[4] = {av.x, av.y, av.z, av.w};
            float b[4] = {bv.x, bv.y, bv.z, bv.w};
            #pragma unroll
            for (int i = 0; i < 4; i++)
                #pragma unroll
                for (int j = 0; j < 4; j++)
                    acc[i][j] += a[i] * b[j];
        }
        __syncthreads();
    }
    #pragma unroll
    for (int i = 0; i < 4; i++) {
        int row = rowBase + ty * 4 + i;
        #pragma unroll
        for (int j = 0; j < 4; j++) {
            int col = tx * 4 + j;
            if (col < Tt)
                C[(size_t)row * Tt + col] = acc[i][j];
        }
    }
}

// ---------------- head-projection GEMM with fused f1/f2 epilogue ----------------
__global__ __launch_bounds__(256)
void gemm_heads_kernel(const float* __restrict__ WhAll, const float* __restrict__ ahAll,
                       int half) {
    int m = blockIdx.x, z = blockIdx.z;
    int hm = z * 4 + m;
    int y = blockIdx.y;
    int b = y / 6, tl = y % 6;
    int rowBase = b * 768 + half * 384 + tl * 64;
    const float* A = g_scratch + OFF_GATIN;
    const float* B = WhAll + (size_t)hm * (Dd * 64);
    float* C = g_scratch + OFF_HH + (size_t)hm * BNROWS * 64;
    __shared__ __align__(16) float As[16][68];
    __shared__ __align__(16) float Bs[16][68];
    int tid = threadIdx.x;
    int tx = tid & 15, ty = tid >> 4;
    float acc[4][4] = {};
    for (int k0 = 0; k0 < Dd; k0 += 16) {
        for (int l = tid; l < 1024; l += 256) {
            int r = l >> 4, kk = l & 15;
            As[kk][r] = A[(size_t)(rowBase + r) * Dd + k0 + kk];
        }
        for (int l = tid; l < 1024; l += 256) {
            int kk = l >> 6, c = l & 63;
            Bs[kk][c] = B[(size_t)(k0 + kk) * 64 + c];
        }
        __syncthreads();
        #pragma unroll
        for (int kk = 0; kk < 16; kk++) {
            float4 av = *(const float4*)&As[kk][ty * 4];
            float4 bv = *(const float4*)&Bs[kk][tx * 4];
            float a[4] = {av.x, av.y, av.z, av.w};
            float b[4] = {bv.x, bv.y, bv.z, bv.w};
            #pragma unroll
            for (int i = 0; i < 4; i++)
                #pragma unroll
                for (int j = 0; j < 4; j++)
                    acc[i][j] += a[i] * b[j];
        }
        __syncthreads();
    }
    const float* a1 = ahAll + (size_t)hm * 128;
    float av1[4], av2[4];
    #pragma unroll
    for (int j = 0; j < 4; j++) {
        av1[j] = a1[tx * 4 + j];
        av2[j] = a1[64 + tx * 4 + j];
    }
    #pragma unroll
    for (int i = 0; i < 4; i++) {
        int row = rowBase + ty * 4 + i;
        float p1 = 0.f, p2 = 0.f;
        float4 cv;
        cv.x = acc[i][0]; cv.y = acc[i][1]; cv.z = acc[i][2]; cv.w = acc[i][3];
        *(float4*)&C[(size_t)row * 64 + tx * 4] = cv;
        #pragma unroll
        for (int j = 0; j < 4; j++) {
            p1 += acc[i][j] * av1[j];
            p2 += acc[i][j] * av2[j];
        }
        #pragma unroll
        for (int off = 8; off > 0; off >>= 1) {
            p1 += __shfl_xor_sync(0xffffffffu, p1, off);
            p2 += __shfl_xor_sync(0xffffffffu, p2, off);
        }
        if (tx == 0) {
            g_scratch[OFF_F1 + (size_t)hm * BNROWS + row] = p1;
            g_scratch[OFF_F2 + (size_t)hm * BNROWS + row] = p2;
        }
    }
}

// ---------------- BiLSTM (round-11 form) ----------------
__global__ __launch_bounds__(256)
void lstm_kernel(const float* __restrict__ whh_f, const float* __restrict__ whh_b) {
    int dir = blockIdx.x & 1, b = blockIdx.x >> 1;
    const float* whh = dir ? whh_b : whh_f;
    int g = threadIdx.x;
    float w[64];
    #pragma unroll
    for (int j = 0; j < 64; j++) w[j] = whh[g * 64 + j];
    __shared__ __align__(16) float hsh[64];
    __shared__ float gates[256];
    float creg = 0.f;
    if (g < 64) hsh[g] = 0.f;
    __syncthreads();
    const float* xwd = g_scratch + OFF_XW + (size_t)dir * BSROWS * 256
                       + (size_t)b * Ss * 256;
    float* gat_in = g_scratch + OFF_GATIN;
    int t = dir ? (Ss - 1) : 0;
    int dt = dir ? -1 : 1;
    bool iscell = (g >= 128 && g < 192);
    float xnext = xwd[(size_t)t * 256 + g];
    for (int step = 0; step < Ss; step++, t += dt) {
        float acc = xnext;
        if (step + 1 < Ss) xnext = xwd[(size_t)(t + dt) * 256 + g];
        const float4* h4 = (const float4*)hsh;
        float a0 = 0.f, a1 = 0.f, a2 = 0.f, a3 = 0.f;
        #pragma unroll
        for (int j4 = 0; j4 < 16; j4++) {
            float4 hv = h4[j4];
            a0 += hv.x * w[4 * j4];
            a1 += hv.y * w[4 * j4 + 1];
            a2 += hv.z * w[4 * j4 + 2];
            a3 += hv.w * w[4 * j4 + 3];
        }
        acc += (a0 + a1) + (a2 + a3);
        gates[g] = iscell ? ftanh(acc) : fsig(acc);
        __syncthreads();
        if (g < 64) {
            creg = gates[64 + g] * creg + gates[g] * gates[128 + g];
            float h = gates[192 + g] * ftanh(creg);
            hsh[g] = h;
            gat_in[((size_t)b * NTOK + t) * Dd + dir * 64 + g] = h;
        }
        __syncthreads();
    }
}

// ---------------- GAT layer-1 aggregation (bitmask adjacency) ----------------
__global__ __launch_bounds__(256)
void attn1_agg_kernel() {
    extern __shared__ __align__(16) float smem[];
    float* hsm = smem;
    float* f2s = smem + 49152;
    float2* psj = (float2*)(smem + 49152 + 768);
    int z = blockIdx.z;
    int m = blockIdx.y >> 4, b = blockIdx.y & 15;
    int chunk = blockIdx.x;
    int hm = z * 4 + m;
    int tid = threadIdx.x, lane = tid & 31, w = tid >> 5;
    const unsigned* abm = (const unsigned*)(g_scratch + OFF_ABM)
                          + ((size_t)z * BNROWS + (size_t)b * 768) * 24;

    const float4* hsrc = (const float4*)(g_scratch + OFF_HH
                         + ((size_t)hm * BNROWS + (size_t)b * 768) * 64);
    float4* hdst = (float4*)hsm;
    for (int l = tid; l < 12288; l += 256) hdst[l] = hsrc[l];
    const float* f2g = g_scratch + OFF_F2 + (size_t)hm * BNROWS + (size_t)b * 768;
    for (int l = tid; l < 768; l += 256) f2s[l] = f2g[l];
    __syncthreads();

    float2* mypsj = psj + w * 256;
    const float* f1g = g_scratch + OFF_F1 + (size_t)hm * BNROWS + (size_t)b * 768;
    float* hcat = g_scratch + OFF_HCAT + (size_t)z * BNROWS * 256;
    const float2* h2p = (const float2*)hsm;

    for (int i = chunk * 384 + w; i < chunk * 384 + 384; i += 8) {
        unsigned word = (lane < 24) ? abm[(size_t)i * 24 + lane] : 0u;
        int c = __popc(word);
        int pos = c;
        #pragma unroll
        for (int off = 1; off < 32; off <<= 1) {
            int n = __shfl_up_sync(0xffffffffu, pos, off);
            if (lane >= off) pos += n;
        }
        int nnz = __shfl_sync(0xffffffffu, pos, 31);
        pos -= c;
        float f1i = f1g[i];
        unsigned wtmp = word;
        while (wtmp) {
            int r = __ffs(wtmp) - 1;
            wtmp &= wtmp - 1;
            int j = lane * 32 + r;
            float e = f1i + f2s[j];
            e = e > 0.f ? e : 0.2f * e;
            mypsj[pos] = make_float2(e, __int_as_float(j));
            pos++;
        }
        __syncwarp();
        float mx = -3e38f;
        for (int idx = lane; idx < nnz; idx += 32) mx = fmaxf(mx, mypsj[idx].x);
        #pragma unroll
        for (int off = 16; off > 0; off >>= 1)
            mx = fmaxf(mx, __shfl_xor_sync(0xffffffffu, mx, off));
        float sm = 0.f;
        for (int idx = lane; idx < nnz; idx += 32) {
            float p = expf(mypsj[idx].x - mx);
            mypsj[idx].x = p;
            sm += p;
        }
        #pragma unroll
        for (int off = 16; off > 0; off >>= 1)
            sm += __shfl_xor_sync(0xffffffffu, sm, off);
        __syncwarp();
        float2 acc = make_float2(0.f, 0.f);
        for (int idx = 0; idx < nnz; idx++) {
            float2 pj = mypsj[idx];
            int j = __float_as_int(pj.y);
            float2 hv = h2p[j * 32 + lane];
            acc.x += pj.x * hv.x;
            acc.y += pj.x * hv.y;
        }
        acc.x /= sm;
        acc.y /= sm;
        acc.x = acc.x > 0.f ? acc.x : expm1f(acc.x);
        acc.y = acc.y > 0.f ? acc.y : expm1f(acc.y);
        ((float2*)(hcat + ((size_t)b * 768 + i) * 256 + m * 64))[lane] = acc;
        __syncwarp();
    }
}

// ---------------- GAT layer-2 (bitmask adjacency, fused f1b/f2b) ----------------
__global__ __launch_bounds__(256)
void attn2_panel_kernel(const float* __restrict__ aoAll) {
    extern __shared__ __align__(16) float smem[];
    float* h2sm = smem;
    float* f2s = smem + 16128;
    float2* psj = (float2*)(smem + 16128 + 768);
    int b = blockIdx.x, z = blockIdx.y;
    const float* ao = aoAll + (size_t)z * 42;
    const float* h2g = g_scratch + OFF_H2 + ((size_t)z * BNROWS + (size_t)b * 768) * 21;
    int tid = threadIdx.x, lane = tid & 31, w = tid >> 5;
    const unsigned* abm = (const unsigned*)(g_scratch + OFF_ABM)
                          + ((size_t)z * BNROWS + (size_t)b * 768) * 24;

    for (int l = tid; l < 16128; l += 256) h2sm[l] = h2g[l];
    __syncthreads();
    for (int j = tid; j < 768; j += 256) {
        float s = 0.f;
        #pragma unroll
        for (int t = 0; t < 21; t++) s += h2sm[j * 21 + t] * ao[21 + t];
        f2s[j] = s;
    }
    __syncthreads();

    float2* mypsj = psj + w * 256;
    float* gout = g_scratch + OFF_GOUT + (size_t)z * BSROWS * Tt;
    float ao1 = (lane < 21) ? ao[lane] : 0.f;

    for (int i = w; i < Ss; i += 8) {
        float f1i = (lane < 21) ? h2sm[i * 21 + lane] * ao1 : 0.f;
        #pragma unroll
        for (int off = 16; off > 0; off >>= 1)
            f1i += __shfl_xor_sync(0xffffffffu, f1i, off);
        unsigned word = (lane < 24) ? abm[(size_t)i * 24 + lane] : 0u;
        int c = __popc(word);
        int pos = c;
        #pragma unroll
        for (int off = 1; off < 32; off <<= 1) {
            int n = __shfl_up_sync(0xffffffffu, pos, off);
            if (lane >= off) pos += n;
        }
        int nnz = __shfl_sync(0xffffffffu, pos, 31);
        pos -= c;
        unsigned wtmp = word;
        while (wtmp) {
            int r = __ffs(wtmp) - 1;
            wtmp &= wtmp - 1;
            int j = lane * 32 + r;
            float e = f1i + f2s[j];
            e = e > 0.f ? e : 0.2f * e;
            mypsj[pos] = make_float2(e, __int_as_float(j));
            pos++;
        }
        __syncwarp();
        float mx = -3e38f;
        for (int idx = lane; idx < nnz; idx += 32) mx = fmaxf(mx, mypsj[idx].x);
        #pragma unroll
        for (int off = 16; off > 0; off >>= 1)
            mx = fmaxf(mx, __shfl_xor_sync(0xffffffffu, mx, off));
        float sm = 0.f;
        for (int idx = lane; idx < nnz; idx += 32) {
            float p = expf(mypsj[idx].x - mx);
            mypsj[idx].x = p;
            sm += p;
        }
        #pragma unroll
        for (int off = 16; off > 0; off >>= 1)
            sm += __shfl_xor_sync(0xffffffffu, sm, off);
        __syncwarp();
        if (lane < 21) {
            float acc = 0.f;
            for (int idx = 0; idx < nnz; idx++) {
                float2 pj = mypsj[idx];
                int j = __float_as_int(pj.y);
                acc += pj.x * h2sm[j * 21 + lane];
            }
            acc /= sm;
            acc = acc > 0.f ? acc : expm1f(acc);
            gout[((size_t)b * Ss + i) * 21 + lane] = acc;
        }
        __syncwarp();
    }
}

// ---------------- fuse ----------------
__global__ void fuse_kernel(const float* __restrict__ fw) {
    int i = blockIdx.x * blockDim.x + threadIdx.x;
    if (i >= Bb * Ss * Tt) return;
    const float* lproj = g_scratch + OFF_LPROJ;
    const float* g0 = g_scratch + OFF_GOUT;
    const float* g1 = g0 + BSROWS * Tt;
    const float* g2 = g1 + BSROWS * Tt;
    g_scratch[OFF_FEATS + i] =
        fw[0] * lproj[i] + fw[1] * g0[i] + fw[2] * g1[i] + fw[3] * g2[i];
}

// ---------------- Viterbi (float32 output) ----------------
__global__ __launch_bounds__(32)
void viterbi_kernel(const float* __restrict__ trans,
                    const int* __restrict__ mask, float* __restrict__ outv) {
    const float* feats = g_scratch + OFF_FEATS;
    int b = blockIdx.x;
    int tid = threadIdx.x;
    __shared__ float part[21], np[21];
    __shared__ float trsh[441];
    __shared__ short bps[Ss * Tt];
    __shared__ int tags[Ss];
    for (int l = tid; l < 441; l += 32) trsh[l] = trans[l];
    __syncthreads();
    if (tid < 21)
        part[tid] = feats[((size_t)b * Ss) * Tt + tid] + trsh[CSTART * 21 + tid];
    __syncthreads();
    for (int t = 1; t < Ss; t++) {
        if (tid < 21) {
            float ft = feats[((size_t)b * Ss + t) * Tt + tid];
            float best = -3e38f; int bi = 0;
            #pragma unroll
            for (int p = 0; p < 21; p++) {
                float v = part[p] + trsh[p * 21 + tid] + ft;
                if (v > best) { best = v; bi = p; }
            }
            int m = mask[b * Ss + t];
            np[tid] = (m > 0) ? best : part[tid];
            bps[t * Tt + tid] = (short)((m > 0) ? bi : tid);
        }
        __syncthreads();
        if (tid < 21) part[tid] = np[tid];
        __syncthreads();
    }
    if (tid == 0) {
        float best = -3e38f; int bt = 0;
        for (int p = 0; p < 21; p++) {
            float v = part[p] + trsh[p * 21 + CSTOP];
            if (v > best) { best = v; bt = p; }
        }
        tags[Ss - 1] = bt;
        int tag = bt;
        for (int t = Ss - 1; t >= 1; t--) {
            tag = (int)bps[t * Tt + tag];
            tags[t - 1] = tag;
        }
    }
    __syncthreads();
    for (int t = tid; t < Ss; t += 32)
        outv[(size_t)b * Ss + t] = (float)tags[t];
}

// ---------------- launch ----------------
extern "C" void kernel_launch(void* const* d_in, const int* in_sizes, int n_in,
                              void* d_out, int out_size) {
    const int*   batch_char = (const int*)d_in[0];
    const int*   gaz_list   = (const int*)d_in[2];
    const int*   adj0       = (const int*)d_in[3];
    const int*   adj1       = (const int*)d_in[4];
    const int*   adj2       = (const int*)d_in[5];
    const int*   mask       = (const int*)d_in[6];
    const float* char_table = (const float*)d_in[7];
    const float* gaz_table  = (const float*)d_in[8];
    const float* w_ih_f     = (const float*)d_in[9];
    const float* w_hh_f     = (const float*)d_in[10];
    const float* b_f        = (const float*)d_in[11];
    const float* w_ih_b     = (const float*)d_in[12];
    const float* w_hh_b     = (const float*)d_in[13];
    const float* b_b        = (const float*)d_in[14];
    const float* h2h_W      = (const float*)d_in[15];
    const float* h2h_b      = (const float*)d_in[16];
    const float* gat_Wh     = (const float*)d_in[17];
    const float* gat_ah     = (const float*)d_in[18];
    const float* gat_Wo     = (const float*)d_in[19];
    const float* gat_ao     = (const float*)d_in[20];
    const float* fuse_w     = (const float*)d_in[21];
    const float* trans      = (const float*)d_in[22];

    static cudaStream_t s1 = nullptr;
    static cudaEvent_t evA = nullptr, evB = nullptr, evL = nullptr;
    if (!s1) {
        cudaStreamCreate(&s1);
        cudaEventCreateWithFlags(&evA, cudaEventDisableTiming);
        cudaEventCreateWithFlags(&evB, cudaEventDisableTiming);
        cudaEventCreateWithFlags(&evL, cudaEventDisableTiming);
    }
    cudaFuncSetAttribute(attn1_agg_kernel,
                         cudaFuncAttributeMaxDynamicSharedMemorySize, SMEM_ATTN1);
    cudaFuncSetAttribute(attn2_panel_kernel,
                         cudaFuncAttributeMaxDynamicSharedMemorySize, SMEM_ATTN2);

    // fork: side stream does adjacency bitmasks + gaz embedding + gaz-half heads
    cudaEventRecord(evA, 0);
    cudaStreamWaitEvent(s1, evA, 0);
    adj_bitmask_kernel<<<(3 * BNROWS + 7) / 8, 256, 0, s1>>>(adj0, adj1, adj2);
    embed_gaz_kernel<<<(Bb * Gg * Dd + 255) / 256, 256, 0, s1>>>(gaz_list, gaz_table);
    gemm_heads_kernel<<<dim3(4, 96, 3), 256, 0, s1>>>(gat_Wh, gat_ah, 1);

    // main stream: xw GEMM -> lstm; lproj moves to side stream (overlaps heads half 0)
    gemm_xw_kernel<<<dim3(8, 96), 256>>>(char_table, batch_char,
                                         w_ih_f, b_f, w_ih_b, b_b);
    lstm_kernel<<<32, 256>>>(w_hh_f, w_hh_b);
    cudaEventRecord(evL, 0);
    cudaStreamWaitEvent(s1, evL, 0);
    gemm_kernel<<<dim3(1, 96), 256, 0, s1>>>(OFF_GATIN, h2h_W, h2h_b,
                                             OFF_LPROJ, BSROWS, Tt, Dd, 1, Ss, NTOK);
    cudaEventRecord(evB, s1);
    gemm_heads_kernel<<<dim3(4, 96, 3), 256>>>(gat_Wh, gat_ah, 0);

    // join, then the rest of the GAT pipeline
    cudaStreamWaitEvent(0, evB, 0);
    attn1_agg_kernel<<<dim3(2, 64, 3), 256, SMEM_ATTN1>>>();
    gemm_h2_kernel<<<dim3(1, 192, 3), 256>>>(gat_Wo);
    attn2_panel_kernel<<<dim3(Bb, 3), 256, SMEM_ATTN2>>>(gat_ao);

    fuse_kernel<<<(Bb * Ss * Tt + 255) / 256, 256>>>(fuse_w);
    viterbi_kernel<<<Bb, 32>>>(trans, mask, (float*)d_out);
}